// round 14
// baseline (speedup 1.0000x reference)
#include <cuda_runtime.h>
#include <cuda_fp16.h>
#include <cstdint>

// PolyLoss: N=4096 rows, V=128 circular shifts, last dim = 2.
// per_shift[n,s] = (1/V) sum_v |pred[n,(s+v)%V] - gt[n,v]|_1 ; loss = mean_n min_s
//
// Identity: |a-b| = a + b - 2*min(a,b); sum_v (p+g) = P+G is shift-invariant:
//   min_s per_shift = ( (P+G) - 2 * max_s sum_v min(p_{s+v}, g_v) ) / V.
// fp16x2 inner loop: min.f16x2 (alu) + add.rn.f16x2 (fma) = 2 slots/pair.
// fp16 accumulators fold to 4 fp32 scalars every 16 v (chain <= 16 adds).
// P+G computed in fp32 at staging.
//
// R14: register diet (fold to 4 fp32, not 8) + __launch_bounds__(128,16)
// -> 16 CTAs/SM -> grid 2048 fits in ONE wave (was 12 CTAs/SM, 1.15 waves).

#define NROWS 4096
#define V 128
#define NCTA 2048
#define THREADS 128

__device__ float g_partial[NCTA];
__device__ int g_ctr;

__device__ __forceinline__ uint32_t hmin2(uint32_t a, uint32_t b) {
    uint32_t d;
    asm("min.f16x2 %0, %1, %2;" : "=r"(d) : "r"(a), "r"(b));
    return d;
}
__device__ __forceinline__ uint32_t hadd2(uint32_t a, uint32_t b) {
    uint32_t d;
    asm("add.rn.f16x2 %0, %1, %2;" : "=r"(d) : "r"(a), "r"(b));
    return d;
}
__device__ __forceinline__ float2 h2f(uint32_t h) {
    __half2 hv = *reinterpret_cast<__half2*>(&h);
    return __half22float2(hv);
}
__device__ __forceinline__ uint32_t pack_h2(float x, float y) {
    __half2 hv = __float22half2_rn(make_float2(x, y));
    return *reinterpret_cast<uint32_t*>(&hv);
}

// acc(f16x2) += min(p, g): 1x HMNMX2 (alu) + 1x HADD2 (fma)
#define ACC(acc, P, G) (acc) = hadd2((acc), hmin2((P), (G)))

__global__ void __launch_bounds__(THREADS, 16) polyloss_kernel(
    const float* __restrict__ pred, const float* __restrict__ gt,
    float* __restrict__ out)
{
    // sp[k] = fp16x2 of position k's 2 components; k=0..255 (circular dup).
    // sg[k] = gt position k, k=0..127. uint4-aligned for LDS.128.
    __shared__ __align__(16) uint32_t sp[2][256];
    __shared__ __align__(16) uint32_t sg[2][128];
    __shared__ float4 ssum[4][32];
    __shared__ float sPG[4];
    __shared__ float s_rowmin[2];
    __shared__ int s_is_last;
    __shared__ float s_red[THREADS];

    const int tid  = threadIdx.x;
    const int w    = tid >> 5;
    const int lane = tid & 31;
    const int rl   = w >> 1;     // row within CTA (0,1)
    const int half = w & 1;      // v-half this warp covers

    // ---- stage 2 rows, 64 threads each: i<32 -> pred uint4 i (positions
    //      4i..4i+3), i>=32 -> gt uint4 i-32. fp32 P+G reduced per warp. ----
    {
        const int rr = tid >> 6;
        const int i  = tid & 63;
        const int rowg = blockIdx.x * 2 + rr;
        float4 v0, v1;
        if (i < 32) {
            const float4* prow = reinterpret_cast<const float4*>(pred) + rowg * 64;
            v0 = prow[2 * i];
            v1 = prow[2 * i + 1];
        } else {
            const float4* grow = reinterpret_cast<const float4*>(gt) + rowg * 64;
            v0 = grow[2 * (i - 32)];
            v1 = grow[2 * (i - 32) + 1];
        }
        uint4 packed = make_uint4(pack_h2(v0.x, v0.y), pack_h2(v0.z, v0.w),
                                  pack_h2(v1.x, v1.y), pack_h2(v1.z, v1.w));
        if (i < 32) {
            *reinterpret_cast<uint4*>(&sp[rr][4 * i])       = packed;
            *reinterpret_cast<uint4*>(&sp[rr][4 * i + 128]) = packed;  // dup
        } else {
            *reinterpret_cast<uint4*>(&sg[rr][4 * (i - 32)]) = packed;
        }
        // fp32 P+G: each float counted exactly once across the 64 threads
        float pg = ((v0.x + v0.y) + (v0.z + v0.w)) + ((v1.x + v1.y) + (v1.z + v1.w));
        #pragma unroll
        for (int off = 16; off > 0; off >>= 1)
            pg += __shfl_xor_sync(0xffffffffu, pg, off);
        if (lane == 0) sPG[w] = pg;
    }
    __syncthreads();

    // ---- mainloop: 16 blocks x 4 v's. Window = 8 consecutive positions
    //      starting at 4*(lane+16*half+m); one new LDS.128 + one G LDS.128
    //      per block. Fold fp16 accs to fp32 every 4 blocks (16 adds max). ----
    uint32_t a0 = 0, a1 = 0, a2 = 0, a3 = 0;     // fp16x2 accumulators
    float m0 = 0.f, m1 = 0.f, m2 = 0.f, m3 = 0.f;
    const uint4* wp = reinterpret_cast<const uint4*>(&sp[rl][0]) + lane + 16 * half;
    const uint4* gp = reinterpret_cast<const uint4*>(&sg[rl][0]) + 16 * half;

    uint4 W0 = wp[0];
    #pragma unroll
    for (int m = 0; m < 16; m++) {
        uint4 G  = gp[m];        // gt[v0..v0+3], broadcast
        uint4 W1 = wp[m + 1];    // next 4 positions (CSE: next iter's W0)
        // u=0: positions +0..+3
        ACC(a0, W0.x, G.x); ACC(a1, W0.y, G.x); ACC(a2, W0.z, G.x); ACC(a3, W0.w, G.x);
        // u=1: positions +1..+4
        ACC(a0, W0.y, G.y); ACC(a1, W0.z, G.y); ACC(a2, W0.w, G.y); ACC(a3, W1.x, G.y);
        // u=2: positions +2..+5
        ACC(a0, W0.z, G.z); ACC(a1, W0.w, G.z); ACC(a2, W1.x, G.z); ACC(a3, W1.y, G.z);
        // u=3: positions +3..+6
        ACC(a0, W0.w, G.w); ACC(a1, W1.x, G.w); ACC(a2, W1.y, G.w); ACC(a3, W1.z, G.w);
        W0 = W1;
        if ((m & 3) == 3) {   // fold to fp32 scalars, reset fp16 accumulators
            float2 f;
            f = h2f(a0); m0 += f.x + f.y; a0 = 0;
            f = h2f(a1); m1 += f.x + f.y; a1 = 0;
            f = h2f(a2); m2 += f.x + f.y; a2 = 0;
            f = h2f(a3); m3 += f.x + f.y; a3 = 0;
        }
    }

    // ---- per-(thread,shift) min-sum partials -> smem ----
    ssum[w][lane] = make_float4(m0, m1, m2, m3);
    __syncthreads();

    // ---- combine v-halves, MAX over shifts, rowmin = PG - 2*max ----
    if (w < 2) {
        float PG = sPG[2 * w] + sPG[2 * w + 1];
        float4 x = ssum[2 * w][lane];
        float4 y = ssum[2 * w + 1][lane];
        float t0 = x.x + y.x, t1 = x.y + y.y, t2 = x.z + y.z, t3 = x.w + y.w;
        float mx = fmaxf(fmaxf(t0, t1), fmaxf(t2, t3));
        #pragma unroll
        for (int off = 16; off > 0; off >>= 1)
            mx = fmaxf(mx, __shfl_xor_sync(0xffffffffu, mx, off));
        if (lane == 0) s_rowmin[w] = PG - 2.0f * mx;
    }
    __syncthreads();

    // ---- CTA partial + last-CTA ticket reduction ----
    if (tid == 0) {
        g_partial[blockIdx.x] = s_rowmin[0] + s_rowmin[1];
        __threadfence();
        int ticket = atomicAdd(&g_ctr, 1);
        s_is_last = (ticket == NCTA - 1);
    }
    __syncthreads();

    if (s_is_last) {
        __threadfence();
        float acc = 0.f;
        #pragma unroll
        for (int i = tid; i < NCTA; i += THREADS)
            acc += g_partial[i];
        s_red[tid] = acc;
        __syncthreads();
        #pragma unroll
        for (int off = THREADS / 2; off > 0; off >>= 1) {
            if (tid < off) s_red[tid] += s_red[tid + off];
            __syncthreads();
        }
        if (tid == 0) {
            out[0] = s_red[0] * (1.0f / ((float)NROWS * (float)V));
            g_ctr = 0;  // reset for next graph replay
        }
    }
}

extern "C" void kernel_launch(void* const* d_in, const int* in_sizes, int n_in,
                              void* d_out, int out_size)
{
    const float* pred = (const float*)d_in[0];
    const float* gt   = (const float*)d_in[1];
    polyloss_kernel<<<NCTA, THREADS>>>(pred, gt, (float*)d_out);
}

// round 15
// speedup vs baseline: 1.0898x; 1.0898x over previous
#include <cuda_runtime.h>
#include <cuda_fp16.h>
#include <cstdint>

// PolyLoss: N=4096 rows, V=128 circular shifts, last dim = 2.
// per_shift[n,s] = (1/V) sum_v |pred[n,(s+v)%V] - gt[n,v]|_1 ; loss = mean_n min_s
//
// Identity: |a-b| = a + b - 2*min(a,b); sum_v (p+g) = P+G is shift-invariant:
//   min_s per_shift = ( (P+G) - 2 * max_s sum_v min(p_{s+v}, g_v) ) / V.
// fp16x2 inner loop: min.f16x2 (alu) + add.rn.f16x2 (fma) = 2 slots/pair.
// fp16 accumulators fold to 4 fp32 scalars every 32 v (chain <= 32 adds,
// est rel err ~6e-6). P+G computed in fp32 at staging.
//
// R15: 4 rows per 256-thread CTA (grid 1024, single wave at 8 CTAs/SM),
// fold every 8 iters, shorter fused final reduction (4 LDG rounds).

#define NROWS 4096
#define V 128
#define RPC 4
#define NCTA (NROWS / RPC)    // 1024
#define THREADS 256

__device__ float g_partial[NCTA];
__device__ int g_ctr;

__device__ __forceinline__ uint32_t hmin2(uint32_t a, uint32_t b) {
    uint32_t d;
    asm("min.f16x2 %0, %1, %2;" : "=r"(d) : "r"(a), "r"(b));
    return d;
}
__device__ __forceinline__ uint32_t hadd2(uint32_t a, uint32_t b) {
    uint32_t d;
    asm("add.rn.f16x2 %0, %1, %2;" : "=r"(d) : "r"(a), "r"(b));
    return d;
}
__device__ __forceinline__ float2 h2f(uint32_t h) {
    __half2 hv = *reinterpret_cast<__half2*>(&h);
    return __half22float2(hv);
}
__device__ __forceinline__ uint32_t pack_h2(float x, float y) {
    __half2 hv = __float22half2_rn(make_float2(x, y));
    return *reinterpret_cast<uint32_t*>(&hv);
}

// acc(f16x2) += min(p, g): 1x HMNMX2 (alu) + 1x HADD2 (fma)
#define ACC(acc, P, G) (acc) = hadd2((acc), hmin2((P), (G)))

__global__ void __launch_bounds__(THREADS, 8) polyloss_kernel(
    const float* __restrict__ pred, const float* __restrict__ gt,
    float* __restrict__ out)
{
    // sp[k] = fp16x2 of position k's 2 components; k=0..255 (circular dup).
    // sg[k] = gt position k, k=0..127. uint4-aligned for LDS.128.
    __shared__ __align__(16) uint32_t sp[RPC][256];
    __shared__ __align__(16) uint32_t sg[RPC][128];
    __shared__ float4 ssum[2 * RPC][32];
    __shared__ float sPG[2 * RPC];
    __shared__ float s_rowmin[RPC];
    __shared__ int s_is_last;
    __shared__ float s_red[THREADS];

    const int tid  = threadIdx.x;
    const int w    = tid >> 5;          // 0..7
    const int lane = tid & 31;
    const int rl   = w >> 1;            // row within CTA (0..3)
    const int half = w & 1;             // v-half this warp covers

    // ---- stage 4 rows, 64 threads each: i<32 -> pred uint4 i (positions
    //      4i..4i+3), i>=32 -> gt uint4 i-32. fp32 P+G reduced per warp. ----
    {
        const int rr = tid >> 6;
        const int i  = tid & 63;
        const int rowg = blockIdx.x * RPC + rr;
        float4 v0, v1;
        if (i < 32) {
            const float4* prow = reinterpret_cast<const float4*>(pred) + rowg * 64;
            v0 = prow[2 * i];
            v1 = prow[2 * i + 1];
        } else {
            const float4* grow = reinterpret_cast<const float4*>(gt) + rowg * 64;
            v0 = grow[2 * (i - 32)];
            v1 = grow[2 * (i - 32) + 1];
        }
        uint4 packed = make_uint4(pack_h2(v0.x, v0.y), pack_h2(v0.z, v0.w),
                                  pack_h2(v1.x, v1.y), pack_h2(v1.z, v1.w));
        if (i < 32) {
            *reinterpret_cast<uint4*>(&sp[rr][4 * i])       = packed;
            *reinterpret_cast<uint4*>(&sp[rr][4 * i + 128]) = packed;  // dup
        } else {
            *reinterpret_cast<uint4*>(&sg[rr][4 * (i - 32)]) = packed;
        }
        // fp32 P+G: each float counted exactly once across the 64 threads
        float pg = ((v0.x + v0.y) + (v0.z + v0.w)) + ((v1.x + v1.y) + (v1.z + v1.w));
        #pragma unroll
        for (int off = 16; off > 0; off >>= 1)
            pg += __shfl_xor_sync(0xffffffffu, pg, off);
        if (lane == 0) sPG[w] = pg;
    }
    __syncthreads();

    // ---- mainloop: 16 blocks x 4 v's. Window = 8 consecutive positions
    //      starting at 4*(lane+16*half+m); one new LDS.128 + one G LDS.128
    //      per block. Fold fp16 accs to fp32 every 8 blocks (32 adds max). ----
    uint32_t a0 = 0, a1 = 0, a2 = 0, a3 = 0;     // fp16x2 accumulators
    float m0 = 0.f, m1 = 0.f, m2 = 0.f, m3 = 0.f;
    const uint4* wp = reinterpret_cast<const uint4*>(&sp[rl][0]) + lane + 16 * half;
    const uint4* gp = reinterpret_cast<const uint4*>(&sg[rl][0]) + 16 * half;

    uint4 W0 = wp[0];
    #pragma unroll
    for (int m = 0; m < 16; m++) {
        uint4 G  = gp[m];        // gt[v0..v0+3], broadcast
        uint4 W1 = wp[m + 1];    // next 4 positions (CSE: next iter's W0)
        // u=0: positions +0..+3
        ACC(a0, W0.x, G.x); ACC(a1, W0.y, G.x); ACC(a2, W0.z, G.x); ACC(a3, W0.w, G.x);
        // u=1: positions +1..+4
        ACC(a0, W0.y, G.y); ACC(a1, W0.z, G.y); ACC(a2, W0.w, G.y); ACC(a3, W1.x, G.y);
        // u=2: positions +2..+5
        ACC(a0, W0.z, G.z); ACC(a1, W0.w, G.z); ACC(a2, W1.x, G.z); ACC(a3, W1.y, G.z);
        // u=3: positions +3..+6
        ACC(a0, W0.w, G.w); ACC(a1, W1.x, G.w); ACC(a2, W1.y, G.w); ACC(a3, W1.z, G.w);
        W0 = W1;
        if ((m & 7) == 7) {   // fold to fp32 scalars, reset fp16 accumulators
            float2 f;
            f = h2f(a0); m0 += f.x + f.y; a0 = 0;
            f = h2f(a1); m1 += f.x + f.y; a1 = 0;
            f = h2f(a2); m2 += f.x + f.y; a2 = 0;
            f = h2f(a3); m3 += f.x + f.y; a3 = 0;
        }
    }

    // ---- per-(thread,shift) min-sum partials -> smem ----
    ssum[w][lane] = make_float4(m0, m1, m2, m3);
    __syncthreads();

    // ---- combine v-halves, MAX over shifts, rowmin = PG - 2*max ----
    if (w < RPC) {
        float PG = sPG[2 * w] + sPG[2 * w + 1];
        float4 x = ssum[2 * w][lane];
        float4 y = ssum[2 * w + 1][lane];
        float t0 = x.x + y.x, t1 = x.y + y.y, t2 = x.z + y.z, t3 = x.w + y.w;
        float mx = fmaxf(fmaxf(t0, t1), fmaxf(t2, t3));
        #pragma unroll
        for (int off = 16; off > 0; off >>= 1)
            mx = fmaxf(mx, __shfl_xor_sync(0xffffffffu, mx, off));
        if (lane == 0) s_rowmin[w] = PG - 2.0f * mx;
    }
    __syncthreads();

    // ---- CTA partial + last-CTA ticket reduction ----
    if (tid == 0) {
        g_partial[blockIdx.x] =
            (s_rowmin[0] + s_rowmin[1]) + (s_rowmin[2] + s_rowmin[3]);
        __threadfence();
        int ticket = atomicAdd(&g_ctr, 1);
        s_is_last = (ticket == NCTA - 1);
    }
    __syncthreads();

    if (s_is_last) {
        __threadfence();
        // 4 independent LDGs (MLP), then pairwise fold
        float r0 = g_partial[tid];
        float r1 = g_partial[tid + 256];
        float r2 = g_partial[tid + 512];
        float r3 = g_partial[tid + 768];
        s_red[tid] = (r0 + r1) + (r2 + r3);
        __syncthreads();
        #pragma unroll
        for (int off = THREADS / 2; off > 0; off >>= 1) {
            if (tid < off) s_red[tid] += s_red[tid + off];
            __syncthreads();
        }
        if (tid == 0) {
            out[0] = s_red[0] * (1.0f / ((float)NROWS * (float)V));
            g_ctr = 0;  // reset for next graph replay
        }
    }
}

extern "C" void kernel_launch(void* const* d_in, const int* in_sizes, int n_in,
                              void* d_out, int out_size)
{
    const float* pred = (const float*)d_in[0];
    const float* gt   = (const float*)d_in[1];
    polyloss_kernel<<<NCTA, THREADS>>>(pred, gt, (float*)d_out);
}